// round 13
// baseline (speedup 1.0000x reference)
#include <cuda_runtime.h>
#include <cuda_bf16.h>
#include <math.h>
#include <stdint.h>

#define BATCH 4
#define LEN   4096
#define DIN   2048
#define NST   16
#define RNK   128
#define M_TOT (BATCH*LEN)   // 16384
#define SCH   16
#define P_SEG 32
#define SEGLEN (LEN/P_SEG)  // 128
#define NCHS  (SEGLEN/SCH)  // 8
#define CPB   128           // channels (=threads) per scan block

typedef unsigned long long u64;

// ---------------------------------------------------------------------------
// Device scratch
// ---------------------------------------------------------------------------
__device__ float g_B [(size_t)M_TOT * NST];
__device__ float g_C [(size_t)M_TOT * NST];
__device__ float g_delta[(size_t)M_TOT * DIN];
__device__ float g_hseg[(size_t)BATCH * P_SEG * DIN * NST];
__device__ float g_pseg[(size_t)BATCH * P_SEG * DIN * NST];
__device__ float g_hin [(size_t)BATCH * P_SEG * DIN * NST];
// bf16 hi/lo split operands (row-major, k contiguous)
__device__ __nv_bfloat16 g_w1h[(size_t)160 * DIN];
__device__ __nv_bfloat16 g_w1l[(size_t)160 * DIN];
__device__ __nv_bfloat16 g_wdh[(size_t)DIN * RNK];
__device__ __nv_bfloat16 g_wdl[(size_t)DIN * RNK];
__device__ __nv_bfloat16 g_dth[(size_t)M_TOT * RNK];
__device__ __nv_bfloat16 g_dtl[(size_t)M_TOT * RNK];

// ---------------------------------------------------------------------------
// helpers
// ---------------------------------------------------------------------------
__device__ __forceinline__ unsigned smem_u32(const void* p) {
    unsigned a;
    asm("{ .reg .u64 t; cvta.to.shared.u64 t, %1; cvt.u32.u64 %0, t; }"
        : "=r"(a) : "l"(p));
    return a;
}
__device__ __forceinline__ u64 pack2f(float lo, float hi) {
    u64 r; asm("mov.b64 %0,{%1,%2};" : "=l"(r) : "f"(lo), "f"(hi)); return r;
}
__device__ __forceinline__ float2 unpack2f(u64 v) {
    float2 f; asm("mov.b64 {%0,%1},%2;" : "=f"(f.x), "=f"(f.y) : "l"(v)); return f;
}
__device__ __forceinline__ u64 ffma2(u64 a, u64 b, u64 c) {
    u64 d; asm("fma.rn.f32x2 %0,%1,%2,%3;" : "=l"(d) : "l"(a), "l"(b), "l"(c)); return d;
}
__device__ __forceinline__ u64 mul2(u64 a, u64 b) {
    return ffma2(a, b, 0ull);
}
// packed powers: e2[k] = (r^(2k+1), r^(2k+2)), k=0..7
__device__ __forceinline__ void pow16p(float r, u64* e2) {
    const float r2 = r * r, r4 = r2 * r2, r8 = r4 * r4;
    const u64 r2p = pack2f(r2, r2);
    const u64 r4p = pack2f(r4, r4);
    const u64 r8p = pack2f(r8, r8);
    e2[0] = pack2f(r, r2);
    e2[1] = mul2(e2[0], r2p);
    e2[2] = mul2(e2[0], r4p);
    e2[3] = mul2(e2[1], r4p);
    e2[4] = mul2(e2[0], r8p);
    e2[5] = mul2(e2[1], r8p);
    e2[6] = mul2(e2[2], r8p);
    e2[7] = mul2(e2[3], r8p);
}
union F4U2 { float4 f4; u64 u2[2]; };

#define CP_ASYNC16(sm, gp) \
    asm volatile("cp.async.cg.shared.global [%0],[%1],16;" :: "r"(sm), "l"(gp) : "memory")
#define CP_COMMIT() asm volatile("cp.async.commit_group;" ::: "memory")
#define CP_WAIT0()  asm volatile("cp.async.wait_group 0;" ::: "memory")

__device__ __forceinline__ void split2(float a, float b, unsigned& h, unsigned& l) {
    __nv_bfloat16 ha = __float2bfloat16(a), hb = __float2bfloat16(b);
    float ra = a - __bfloat162float(ha), rb = b - __bfloat162float(hb);
    __nv_bfloat16 la = __float2bfloat16(ra), lb = __float2bfloat16(rb);
    h = (unsigned)__bfloat16_as_ushort(ha) | ((unsigned)__bfloat16_as_ushort(hb) << 16);
    l = (unsigned)__bfloat16_as_ushort(la) | ((unsigned)__bfloat16_as_ushort(lb) << 16);
}
__device__ __forceinline__ void splitf4(float4 v, uint2& h, uint2& l) {
    split2(v.x, v.y, h.x, l.x);
    split2(v.z, v.w, h.y, l.y);
}
__device__ __forceinline__ void ldsm_x4(unsigned* a, unsigned addr) {
    asm volatile("ldmatrix.sync.aligned.m8n8.x4.shared.b16 {%0,%1,%2,%3}, [%4];"
        : "=r"(a[0]), "=r"(a[1]), "=r"(a[2]), "=r"(a[3]) : "r"(addr));
}
__device__ __forceinline__ void ldsm_x2(unsigned* a, unsigned addr) {
    asm volatile("ldmatrix.sync.aligned.m8n8.x2.shared.b16 {%0,%1}, [%2];"
        : "=r"(a[0]), "=r"(a[1]) : "r"(addr));
}
__device__ __forceinline__ void mma_bf16(float* c, const unsigned* a, const unsigned* b) {
    asm volatile(
        "mma.sync.aligned.m16n8k16.row.col.f32.bf16.bf16.f32 "
        "{%0,%1,%2,%3},{%4,%5,%6,%7},{%8,%9},{%0,%1,%2,%3};"
        : "+f"(c[0]), "+f"(c[1]), "+f"(c[2]), "+f"(c[3])
        : "r"(a[0]), "r"(a[1]), "r"(a[2]), "r"(a[3]), "r"(b[0]), "r"(b[1]));
}

// ---------------------------------------------------------------------------
// PREP (unchanged)
// ---------------------------------------------------------------------------
__global__ __launch_bounds__(256) void prep_kernel(
    const float* __restrict__ W1, const float* __restrict__ Wd)
{
    const int id = blockIdx.x * 256 + threadIdx.x;
    if (id < 81920) {
        const int r = id >> 9, c4 = id & 511;
        float4 v = *(const float4*)(W1 + (size_t)r * DIN + c4 * 4);
        uint2 h, l; splitf4(v, h, l);
        *(uint2*)(g_w1h + (size_t)r * DIN + c4 * 4) = h;
        *(uint2*)(g_w1l + (size_t)r * DIN + c4 * 4) = l;
    } else {
        const int id2 = id - 81920;
        const int r = id2 >> 5, c4 = id2 & 31;
        float4 v = *(const float4*)(Wd + (size_t)r * RNK + c4 * 4);
        uint2 h, l; splitf4(v, h, l);
        *(uint2*)(g_wdh + (size_t)r * RNK + c4 * 4) = h;
        *(uint2*)(g_wdl + (size_t)r * RNK + c4 * 4) = l;
    }
}

// ---------------------------------------------------------------------------
// GEMM1 (unchanged)
// ---------------------------------------------------------------------------
#define G1_AH 0
#define G1_AL 5120
#define G1_BH 10240
#define G1_BL 23040
#define G1_BUF 35840
#define G1_SMEM (2*G1_BUF)

__global__ __launch_bounds__(256, 2) void gemm1_kernel(const float* __restrict__ X)
{
    extern __shared__ __align__(16) char smem[];
    const unsigned sb = smem_u32(smem);
    const int tid = threadIdx.x, lane = tid & 31, w = tid >> 5;
    const int m0 = blockIdx.x * 64;
    const int wm = (w & 1) * 32;
    const int wn = (w >> 1) * 40;

    float acc[2][5][4];
#pragma unroll
    for (int i = 0; i < 2; i++)
#pragma unroll
        for (int j = 0; j < 5; j++)
#pragma unroll
            for (int q = 0; q < 4; q++) acc[i][j][q] = 0.f;

    const int rX0 = tid >> 3, cX0 = (tid & 7) * 4;
    const int rX1 = (tid + 256) >> 3, cX1 = cX0;

    float4 xr[2]; uint4 wr[5];

    auto load_regs = [&](int k0) {
        xr[0] = *(const float4*)(X + (size_t)(m0 + rX0) * DIN + k0 + cX0);
        xr[1] = *(const float4*)(X + (size_t)(m0 + rX1) * DIN + k0 + cX1);
#pragma unroll
        for (int q = 0; q < 5; q++) {
            const int id = q * 256 + tid;
            const __nv_bfloat16* src = (id < 640) ? g_w1h : g_w1l;
            const int rid = (id < 640) ? id : id - 640;
            const int r = rid >> 2, c16 = rid & 3;
            wr[q] = *(const uint4*)(src + (size_t)r * DIN + k0 + c16 * 8);
        }
    };
    auto store_smem = [&](int bi) {
        char* buf = smem + bi * G1_BUF;
        {
            uint2 h, l; splitf4(xr[0], h, l);
            *(uint2*)(buf + G1_AH + 80 * rX0 + 2 * cX0) = h;
            *(uint2*)(buf + G1_AL + 80 * rX0 + 2 * cX0) = l;
            splitf4(xr[1], h, l);
            *(uint2*)(buf + G1_AH + 80 * rX1 + 2 * cX1) = h;
            *(uint2*)(buf + G1_AL + 80 * rX1 + 2 * cX1) = l;
        }
#pragma unroll
        for (int q = 0; q < 5; q++) {
            const int id = q * 256 + tid;
            const int off = (id < 640) ? G1_BH : G1_BL;
            const int rid = (id < 640) ? id : id - 640;
            const int r = rid >> 2, c16 = rid & 3;
            *(uint4*)(buf + off + 80 * r + 16 * c16) = wr[q];
        }
    };
    auto compute = [&](int bi) {
        const unsigned base = sb + bi * G1_BUF;
#pragma unroll
        for (int ks = 0; ks < 2; ks++) {
            const int kc = ks * 16 + ((lane >> 4) & 1) * 8;
            unsigned ah[2][4], al[2][4];
#pragma unroll
            for (int mt = 0; mt < 2; mt++) {
                const int row = wm + mt * 16 + (lane & 15);
                const unsigned ad = base + 80u * row + 2u * kc;
                ldsm_x4(ah[mt], ad + G1_AH);
                ldsm_x4(al[mt], ad + G1_AL);
            }
            unsigned bh[5][2], bl[5][2];
#pragma unroll
            for (int nt = 0; nt < 5; nt++) {
                const int row = wn + nt * 8 + (lane & 7);
                const int col = ks * 16 + ((lane >> 3) & 1) * 8;
                const unsigned bd = base + 80u * row + 2u * col;
                ldsm_x2(bh[nt], bd + G1_BH);
                ldsm_x2(bl[nt], bd + G1_BL);
            }
#pragma unroll
            for (int mt = 0; mt < 2; mt++)
#pragma unroll
                for (int nt = 0; nt < 5; nt++) {
                    mma_bf16(acc[mt][nt], ah[mt], bh[nt]);
                    mma_bf16(acc[mt][nt], ah[mt], bl[nt]);
                    mma_bf16(acc[mt][nt], al[mt], bh[nt]);
                }
        }
    };

    load_regs(0);
    store_smem(0);
    __syncthreads();
    for (int it = 0; it < 64; it++) {
        if (it + 1 < 64) load_regs((it + 1) * 32);
        compute(it & 1);
        if (it + 1 < 64) {
            __syncthreads();
            store_smem((it + 1) & 1);
            __syncthreads();
        }
    }

#pragma unroll
    for (int mt = 0; mt < 2; mt++) {
#pragma unroll
        for (int nt = 0; nt < 5; nt++) {
            const int cb = wn + nt * 8 + 2 * (lane & 3);
            const int mA = m0 + wm + mt * 16 + (lane >> 2);
            const float* c = acc[mt][nt];
            if (cb < RNK) {
                unsigned h, l;
                split2(c[0], c[1], h, l);
                *(unsigned*)(g_dth + (size_t)mA * RNK + cb) = h;
                *(unsigned*)(g_dtl + (size_t)mA * RNK + cb) = l;
                split2(c[2], c[3], h, l);
                *(unsigned*)(g_dth + (size_t)(mA + 8) * RNK + cb) = h;
                *(unsigned*)(g_dtl + (size_t)(mA + 8) * RNK + cb) = l;
            } else if (cb < RNK + NST) {
                *(float2*)(g_B + (size_t)mA * NST + (cb - RNK)) = make_float2(c[0], c[1]);
                *(float2*)(g_B + (size_t)(mA + 8) * NST + (cb - RNK)) = make_float2(c[2], c[3]);
            } else {
                *(float2*)(g_C + (size_t)mA * NST + (cb - RNK - NST)) = make_float2(c[0], c[1]);
                *(float2*)(g_C + (size_t)(mA + 8) * NST + (cb - RNK - NST)) = make_float2(c[2], c[3]);
            }
        }
    }
}

// ---------------------------------------------------------------------------
// GEMM2 (unchanged)
// ---------------------------------------------------------------------------
#define G2_AH 0
#define G2_AL 17408
#define G2_BH 34816
#define G2_BL 69632
#define G2_SMEM 104448

__global__ __launch_bounds__(256, 2) void gemm2_kernel(const float* __restrict__ bias)
{
    extern __shared__ __align__(16) char smem[];
    const unsigned sb = smem_u32(smem);
    const int tid = threadIdx.x, lane = tid & 31, w = tid >> 5;
    const int mt_ = blockIdx.x >> 4;
    const int nt_ = blockIdx.x & 15;
    const int m0 = mt_ * 64, d0 = nt_ * 128;
    const int wm = (w & 1) * 32;
    const int wn = (w >> 1) * 32;

#pragma unroll
    for (int q = 0; q < 8; q++) {
        const int id = q * 256 + tid;
        const __nv_bfloat16* src = (id < 1024) ? g_dth : g_dtl;
        const int off = (id < 1024) ? G2_AH : G2_AL;
        const int rid = id & 1023;
        const int r = rid >> 4, c16 = rid & 15;
        uint4 v = *(const uint4*)(src + (size_t)(m0 + r) * RNK + c16 * 8);
        *(uint4*)(smem + off + 272 * r + 16 * c16) = v;
    }
#pragma unroll
    for (int q = 0; q < 16; q++) {
        const int id = q * 256 + tid;
        const __nv_bfloat16* src = (id < 2048) ? g_wdh : g_wdl;
        const int off = (id < 2048) ? G2_BH : G2_BL;
        const int rid = id & 2047;
        const int r = rid >> 4, c16 = rid & 15;
        uint4 v = *(const uint4*)(src + (size_t)(d0 + r) * RNK + c16 * 8);
        *(uint4*)(smem + off + 272 * r + 16 * c16) = v;
    }
    __syncthreads();

    float acc[2][4][4];
#pragma unroll
    for (int i = 0; i < 2; i++)
#pragma unroll
        for (int j = 0; j < 4; j++)
#pragma unroll
            for (int q = 0; q < 4; q++) acc[i][j][q] = 0.f;

#pragma unroll
    for (int ks = 0; ks < 8; ks++) {
        const int kc = ks * 16 + ((lane >> 4) & 1) * 8;
        unsigned ah[2][4], al[2][4];
#pragma unroll
        for (int mt = 0; mt < 2; mt++) {
            const int row = wm + mt * 16 + (lane & 15);
            const unsigned ad = sb + 272u * row + 2u * kc;
            ldsm_x4(ah[mt], ad + G2_AH);
            ldsm_x4(al[mt], ad + G2_AL);
        }
        unsigned bh[4][2], bl[4][2];
#pragma unroll
        for (int nt = 0; nt < 4; nt++) {
            const int row = wn + nt * 8 + (lane & 7);
            const int col = ks * 16 + ((lane >> 3) & 1) * 8;
            const unsigned bd = sb + 272u * row + 2u * col;
            ldsm_x2(bh[nt], bd + G2_BH);
            ldsm_x2(bl[nt], bd + G2_BL);
        }
#pragma unroll
        for (int mt = 0; mt < 2; mt++)
#pragma unroll
            for (int nt = 0; nt < 4; nt++) {
                mma_bf16(acc[mt][nt], ah[mt], bh[nt]);
                mma_bf16(acc[mt][nt], ah[mt], bl[nt]);
                mma_bf16(acc[mt][nt], al[mt], bh[nt]);
            }
    }

#pragma unroll
    for (int mt = 0; mt < 2; mt++) {
#pragma unroll
        for (int nt = 0; nt < 4; nt++) {
            const int d = d0 + wn + nt * 8 + 2 * (lane & 3);
            const int mA = m0 + wm + mt * 16 + (lane >> 2);
            const float b0v = bias[d], b1v = bias[d + 1];
            const float* c = acc[mt][nt];
            float z0 = c[0] + b0v, z1 = c[1] + b1v;
            float z2 = c[2] + b0v, z3 = c[3] + b1v;
            z0 = (z0 > 20.f) ? z0 : log1pf(__expf(z0));
            z1 = (z1 > 20.f) ? z1 : log1pf(__expf(z1));
            z2 = (z2 > 20.f) ? z2 : log1pf(__expf(z2));
            z3 = (z3 > 20.f) ? z3 : log1pf(__expf(z3));
            *(float2*)(g_delta + (size_t)mA * DIN + d) = make_float2(z0, z1);
            *(float2*)(g_delta + (size_t)(mA + 8) * DIN + d) = make_float2(z2, z3);
        }
    }
}

// ---------------------------------------------------------------------------
// Scan (P_SEG=32): 1 thread/channel, packed f32x2 states, cp.async staging.
// ---------------------------------------------------------------------------
__device__ __forceinline__ void load_A16(const float* A_log, int d, float* A) {
#pragma unroll
    for (int q = 0; q < 4; q++) {
        float4 v = *(const float4*)(A_log + (size_t)d * NST + 4 * q);
        A[4*q+0] = -__expf(v.x); A[4*q+1] = -__expf(v.y);
        A[4*q+2] = -__expf(v.z); A[4*q+3] = -__expf(v.w);
    }
}

__global__ __launch_bounds__(CPB, 5) void scan_seg1_kernel(
    const float* __restrict__ x, const float* __restrict__ A_log)
{
    __shared__ __align__(16) float xs [2][SCH][CPB];
    __shared__ __align__(16) float dsm[2][SCH][CPB];
    __shared__ __align__(16) float Bs [2][SCH][16];

    const int tid  = threadIdx.x;
    const int dg   = blockIdx.x & 15;
    const int bseg = blockIdx.x >> 4;
    const int b    = bseg >> 5;
    const int seg  = bseg & 31;
    const int d    = dg * CPB + tid;

    unsigned fast;
    {
        float A[16];
        load_A16(A_log, d, A);
        bool ok = fabsf(A[0] + 1.f) < 2e-3f;
#pragma unroll
        for (int i = 1; i < 16; i++) ok = ok && (fabsf(A[i] - A[i-1] + 1.f) < 2e-3f);
        fast = __all_sync(0xffffffffu, ok);
    }

    const size_t t0 = (size_t)b * LEN + (size_t)seg * SEGLEN;
    const float* xg  = x       + t0 * DIN + dg * CPB;
    const float* dgp = g_delta + t0 * DIN + dg * CPB;
    const float* Bg  = g_B     + t0 * NST;

    const int rA = tid >> 5;              // rows rA, rA+4, rA+8, rA+12
    const int qA = (tid & 31) * 4;
    const int rB = (tid & 63) >> 2;
    const int qB = (tid & 3) * 4;

    auto issue = [&](int c, int buf) {
        const size_t off = (size_t)c * SCH;
#pragma unroll
        for (int q = 0; q < 4; q++) {
            const int row = rA + 4 * q;
            CP_ASYNC16(smem_u32(&xs [buf][row][qA]), xg  + (off + row) * DIN + qA);
            CP_ASYNC16(smem_u32(&dsm[buf][row][qA]), dgp + (off + row) * DIN + qA);
        }
        if (tid < 64)
            CP_ASYNC16(smem_u32(&Bs[buf][rB][qB]), Bg + (off + rB) * NST + qB);
        CP_COMMIT();
    };

    u64 h2[8];
#pragma unroll
    for (int i = 0; i < 8; i++) h2[i] = 0ull;
    float Sd = 0.f;

    issue(0, 0);
    for (int c = 0; c < NCHS; c++) {
        const int buf = c & 1;
        CP_WAIT0();
        __syncthreads();
        if (c + 1 < NCHS) issue(c + 1, buf ^ 1);

        if (fast) {
#pragma unroll
            for (int j = 0; j < SCH; j++) {
                const float dv = dsm[buf][j][tid];
                const float xv = xs [buf][j][tid];
                F4U2 bb[4];
#pragma unroll
                for (int q = 0; q < 4; q++) bb[q].f4 = *(const float4*)&Bs[buf][j][4 * q];
                const float r = __expf(-dv);
                const float s = dv * xv;
                Sd += dv;
                const u64 s2 = pack2f(s, s);
                u64 e2[8]; pow16p(r, e2);
#pragma unroll
                for (int i = 0; i < 8; i++)
                    h2[i] = ffma2(e2[i], h2[i], mul2(s2, bb[i >> 1].u2[i & 1]));
            }
        } else {
            float A[16];
            load_A16(A_log, d, A);
#pragma unroll
            for (int j = 0; j < SCH; j++) {
                const float dv = dsm[buf][j][tid];
                const float xv = xs [buf][j][tid];
                float Bv[16];
#pragma unroll
                for (int q = 0; q < 4; q++)
                    *(float4*)&Bv[4 * q] = *(const float4*)&Bs[buf][j][4 * q];
                const float s = dv * xv;
                Sd += dv;
#pragma unroll
                for (int i = 0; i < 8; i++) {
                    float2 hh = unpack2f(h2[i]);
                    hh.x = fmaf(__expf(dv * A[2*i]),   hh.x, s * Bv[2*i]);
                    hh.y = fmaf(__expf(dv * A[2*i+1]), hh.y, s * Bv[2*i+1]);
                    h2[i] = pack2f(hh.x, hh.y);
                }
            }
        }
    }

    u64 p2[8];
    if (fast) {
        pow16p(__expf(-Sd), p2);
    } else {
        float A[16];
        load_A16(A_log, d, A);
#pragma unroll
        for (int i = 0; i < 8; i++)
            p2[i] = pack2f(__expf(A[2*i] * Sd), __expf(A[2*i+1] * Sd));
    }
    const size_t hb = (((size_t)(b * P_SEG + seg) * DIN) + d) * NST;
#pragma unroll
    for (int q = 0; q < 4; q++) {
        float2 a = unpack2f(h2[2*q]),   bq = unpack2f(h2[2*q+1]);
        *(float4*)(g_hseg + hb + 4 * q) = make_float4(a.x, a.y, bq.x, bq.y);
        a = unpack2f(p2[2*q]); bq = unpack2f(p2[2*q+1]);
        *(float4*)(g_pseg + hb + 4 * q) = make_float4(a.x, a.y, bq.x, bq.y);
    }
}

__global__ __launch_bounds__(256) void scan_comb_kernel()
{
    const int tid  = threadIdx.x;
    const int cidx = blockIdx.x * 64 + (tid >> 2);
    const int ng   = tid & 3;
    const int b    = cidx >> 11;
    const int d    = cidx & (DIN - 1);

    float4 h = make_float4(0.f, 0.f, 0.f, 0.f);
#pragma unroll
    for (int s = 0; s < P_SEG; s++) {
        const size_t idx = (((size_t)(b * P_SEG + s) * DIN) + d) * NST + 4 * ng;
        *(float4*)(g_hin + idx) = h;
        const float4 Pv = *(const float4*)(g_pseg + idx);
        const float4 Lv = *(const float4*)(g_hseg + idx);
        h.x = fmaf(Pv.x, h.x, Lv.x);
        h.y = fmaf(Pv.y, h.y, Lv.y);
        h.z = fmaf(Pv.z, h.z, Lv.z);
        h.w = fmaf(Pv.w, h.w, Lv.w);
    }
}

__global__ __launch_bounds__(CPB, 5) void scan_seg2_kernel(
    const float* __restrict__ x, const float* __restrict__ A_log,
    const float* __restrict__ Dpar, float* __restrict__ out)
{
    __shared__ __align__(16) float xs [2][SCH][CPB];
    __shared__ __align__(16) float dsm[2][SCH][CPB];
    __shared__ __align__(16) float Bs [2][SCH][16];
    __shared__ __align__(16) float Cs [2][SCH][16];

    const int tid  = threadIdx.x;
    const int dg   = blockIdx.x & 15;
    const int bseg = blockIdx.x >> 4;
    const int b    = bseg >> 5;
    const int seg  = bseg & 31;
    const int d    = dg * CPB + tid;

    unsigned fast;
    {
        float A[16];
        load_A16(A_log, d, A);
        bool ok = fabsf(A[0] + 1.f) < 2e-3f;
#pragma unroll
        for (int i = 1; i < 16; i++) ok = ok && (fabsf(A[i] - A[i-1] + 1.f) < 2e-3f);
        fast = __all_sync(0xffffffffu, ok);
    }
    const float Dd = Dpar[d];

    const size_t t0 = (size_t)b * LEN + (size_t)seg * SEGLEN;
    const float* xg  = x       + t0 * DIN + dg * CPB;
    const float* dgp = g_delta + t0 * DIN + dg * CPB;
    const float* Bg  = g_B     + t0 * NST;
    const float* Cg  = g_C     + t0 * NST;
    float*       og  = out     + t0 * DIN + dg * CPB + tid;

    const int rA = tid >> 5;
    const int qA = (tid & 31) * 4;
    const int rB = (tid & 63) >> 2;
    const int qB = (tid & 3) * 4;

    auto issue = [&](int c, int buf) {
        const size_t off = (size_t)c * SCH;
#pragma unroll
        for (int q = 0; q < 4; q++) {
            const int row = rA + 4 * q;
            CP_ASYNC16(smem_u32(&xs [buf][row][qA]), xg  + (off + row) * DIN + qA);
            CP_ASYNC16(smem_u32(&dsm[buf][row][qA]), dgp + (off + row) * DIN + qA);
        }
        if (tid < 64)
            CP_ASYNC16(smem_u32(&Bs[buf][rB][qB]), Bg + (off + rB) * NST + qB);
        else if (tid < 128)
            CP_ASYNC16(smem_u32(&Cs[buf][rB][qB]), Cg + (off + rB) * NST + qB);
        CP_COMMIT();
    };

    u64 h2[8];
    const size_t hb = (((size_t)(b * P_SEG + seg) * DIN) + d) * NST;
#pragma unroll
    for (int q = 0; q < 4; q++) {
        F4U2 t; t.f4 = *(const float4*)(g_hin + hb + 4 * q);
        h2[2*q]   = t.u2[0];
        h2[2*q+1] = t.u2[1];
    }

    issue(0, 0);
    for (int c = 0; c < NCHS; c++) {
        const int buf = c & 1;
        CP_WAIT0();
        __syncthreads();
        if (c + 1 < NCHS) issue(c + 1, buf ^ 1);
        const size_t off = (size_t)c * SCH;

        if (fast) {
#pragma unroll
            for (int j = 0; j < SCH; j++) {
                const float dv = dsm[buf][j][tid];
                const float xv = xs [buf][j][tid];
                F4U2 bb[4], cc[4];
#pragma unroll
                for (int q = 0; q < 4; q++) {
                    bb[q].f4 = *(const float4*)&Bs[buf][j][4 * q];
                    cc[q].f4 = *(const float4*)&Cs[buf][j][4 * q];
                }
                const float r = __expf(-dv);
                const float s = dv * xv;
                const u64 s2 = pack2f(s, s);
                u64 e2[8]; pow16p(r, e2);
                u64 y2 = 0ull;
#pragma unroll
                for (int i = 0; i < 8; i++) {
                    h2[i] = ffma2(e2[i], h2[i], mul2(s2, bb[i >> 1].u2[i & 1]));
                    y2 = ffma2(h2[i], cc[i >> 1].u2[i & 1], y2);
                }
                const float2 yy = unpack2f(y2);
                og[(off + j) * DIN] = fmaf(Dd, xv, yy.x + yy.y);
            }
        } else {
            float A[16];
            load_A16(A_log, d, A);
#pragma unroll
            for (int j = 0; j < SCH; j++) {
                const float dv = dsm[buf][j][tid];
                const float xv = xs [buf][j][tid];
                float Bv[16], Cv[16];
#pragma unroll
                for (int q = 0; q < 4; q++) {
                    *(float4*)&Bv[4 * q] = *(const float4*)&Bs[buf][j][4 * q];
                    *(float4*)&Cv[4 * q] = *(const float4*)&Cs[buf][j][4 * q];
                }
                const float s = dv * xv;
                float y = 0.f;
#pragma unroll
                for (int i = 0; i < 8; i++) {
                    float2 hh = unpack2f(h2[i]);
                    hh.x = fmaf(__expf(dv * A[2*i]),   hh.x, s * Bv[2*i]);
                    hh.y = fmaf(__expf(dv * A[2*i+1]), hh.y, s * Bv[2*i+1]);
                    y = fmaf(hh.x, Cv[2*i], y);
                    y = fmaf(hh.y, Cv[2*i+1], y);
                    h2[i] = pack2f(hh.x, hh.y);
                }
                og[(off + j) * DIN] = fmaf(Dd, xv, y);
            }
        }
    }
}

// ---------------------------------------------------------------------------
// Launch
// ---------------------------------------------------------------------------
extern "C" void kernel_launch(void* const* d_in, const int* in_sizes, int n_in,
                              void* d_out, int out_size)
{
    const float* x         = (const float*)d_in[0];
    const float* A_log     = (const float*)d_in[1];
    const float* D_param   = (const float*)d_in[2];
    const float* x_proj_w  = (const float*)d_in[3];
    const float* dt_proj_w = (const float*)d_in[4];
    const float* dt_proj_b = (const float*)d_in[5];
    float* out = (float*)d_out;

    cudaFuncSetAttribute(gemm1_kernel, cudaFuncAttributeMaxDynamicSharedMemorySize, G1_SMEM);
    cudaFuncSetAttribute(gemm2_kernel, cudaFuncAttributeMaxDynamicSharedMemorySize, G2_SMEM);

    prep_kernel<<<576, 256>>>(x_proj_w, dt_proj_w);
    gemm1_kernel<<<M_TOT / 64, 256, G1_SMEM>>>(x);
    gemm2_kernel<<<(M_TOT / 64) * (DIN / 128), 256, G2_SMEM>>>(dt_proj_b);
    scan_seg1_kernel<<<BATCH * P_SEG * (DIN / CPB), CPB>>>(x, A_log);
    scan_comb_kernel<<<BATCH * DIN / 64, 256>>>();
    scan_seg2_kernel<<<BATCH * P_SEG * (DIN / CPB), CPB>>>(x, A_log, D_param, out);
}

// round 14
// speedup vs baseline: 1.0926x; 1.0926x over previous
#include <cuda_runtime.h>
#include <cuda_bf16.h>
#include <math.h>
#include <stdint.h>

#define BATCH 4
#define LEN   4096
#define DIN   2048
#define NST   16
#define RNK   128
#define M_TOT (BATCH*LEN)   // 16384
#define SCH   16
#define P_SEG 16
#define SEGLEN (LEN/P_SEG)  // 256
#define NCHS  (SEGLEN/SCH)  // 16
#define CPB   128           // channels (=threads) per scan block

typedef unsigned long long u64;

// ---------------------------------------------------------------------------
// Device scratch
// ---------------------------------------------------------------------------
__device__ float g_B [(size_t)M_TOT * NST];
__device__ float g_C [(size_t)M_TOT * NST];
__device__ float g_delta[(size_t)M_TOT * DIN];
__device__ float g_hseg[(size_t)BATCH * P_SEG * DIN * NST];
__device__ float g_pseg[(size_t)BATCH * P_SEG * DIN * NST];
__device__ float g_hin [(size_t)BATCH * P_SEG * DIN * NST];
// bf16 hi/lo split operands (row-major, k contiguous)
__device__ __nv_bfloat16 g_w1h[(size_t)160 * DIN];
__device__ __nv_bfloat16 g_w1l[(size_t)160 * DIN];
__device__ __nv_bfloat16 g_wdh[(size_t)DIN * RNK];
__device__ __nv_bfloat16 g_wdl[(size_t)DIN * RNK];
__device__ __nv_bfloat16 g_dth[(size_t)M_TOT * RNK];
__device__ __nv_bfloat16 g_dtl[(size_t)M_TOT * RNK];

// ---------------------------------------------------------------------------
// helpers
// ---------------------------------------------------------------------------
__device__ __forceinline__ unsigned smem_u32(const void* p) {
    unsigned a;
    asm("{ .reg .u64 t; cvta.to.shared.u64 t, %1; cvt.u32.u64 %0, t; }"
        : "=r"(a) : "l"(p));
    return a;
}
__device__ __forceinline__ u64 pack2f(float lo, float hi) {
    u64 r; asm("mov.b64 %0,{%1,%2};" : "=l"(r) : "f"(lo), "f"(hi)); return r;
}
__device__ __forceinline__ float2 unpack2f(u64 v) {
    float2 f; asm("mov.b64 {%0,%1},%2;" : "=f"(f.x), "=f"(f.y) : "l"(v)); return f;
}
__device__ __forceinline__ u64 ffma2(u64 a, u64 b, u64 c) {
    u64 d; asm("fma.rn.f32x2 %0,%1,%2,%3;" : "=l"(d) : "l"(a), "l"(b), "l"(c)); return d;
}
__device__ __forceinline__ u64 mul2(u64 a, u64 b) {
    return ffma2(a, b, 0ull);
}
// packed powers: e2[k] = (r^(2k+1), r^(2k+2)), k=0..7
__device__ __forceinline__ void pow16p(float r, u64* e2) {
    const float r2 = r * r, r4 = r2 * r2, r8 = r4 * r4;
    const u64 r2p = pack2f(r2, r2);
    const u64 r4p = pack2f(r4, r4);
    const u64 r8p = pack2f(r8, r8);
    e2[0] = pack2f(r, r2);
    e2[1] = mul2(e2[0], r2p);
    e2[2] = mul2(e2[0], r4p);
    e2[3] = mul2(e2[1], r4p);
    e2[4] = mul2(e2[0], r8p);
    e2[5] = mul2(e2[1], r8p);
    e2[6] = mul2(e2[2], r8p);
    e2[7] = mul2(e2[3], r8p);
}
union F4U2 { float4 f4; u64 u2[2]; };

#define CP_ASYNC16(sm, gp) \
    asm volatile("cp.async.cg.shared.global [%0],[%1],16;" :: "r"(sm), "l"(gp) : "memory")
#define CP_COMMIT() asm volatile("cp.async.commit_group;" ::: "memory")
#define CP_WAIT0()  asm volatile("cp.async.wait_group 0;" ::: "memory")

__device__ __forceinline__ void split2(float a, float b, unsigned& h, unsigned& l) {
    __nv_bfloat16 ha = __float2bfloat16(a), hb = __float2bfloat16(b);
    float ra = a - __bfloat162float(ha), rb = b - __bfloat162float(hb);
    __nv_bfloat16 la = __float2bfloat16(ra), lb = __float2bfloat16(rb);
    h = (unsigned)__bfloat16_as_ushort(ha) | ((unsigned)__bfloat16_as_ushort(hb) << 16);
    l = (unsigned)__bfloat16_as_ushort(la) | ((unsigned)__bfloat16_as_ushort(lb) << 16);
}
__device__ __forceinline__ void splitf4(float4 v, uint2& h, uint2& l) {
    split2(v.x, v.y, h.x, l.x);
    split2(v.z, v.w, h.y, l.y);
}
__device__ __forceinline__ void ldsm_x4(unsigned* a, unsigned addr) {
    asm volatile("ldmatrix.sync.aligned.m8n8.x4.shared.b16 {%0,%1,%2,%3}, [%4];"
        : "=r"(a[0]), "=r"(a[1]), "=r"(a[2]), "=r"(a[3]) : "r"(addr));
}
__device__ __forceinline__ void ldsm_x2(unsigned* a, unsigned addr) {
    asm volatile("ldmatrix.sync.aligned.m8n8.x2.shared.b16 {%0,%1}, [%2];"
        : "=r"(a[0]), "=r"(a[1]) : "r"(addr));
}
__device__ __forceinline__ void mma_bf16(float* c, const unsigned* a, const unsigned* b) {
    asm volatile(
        "mma.sync.aligned.m16n8k16.row.col.f32.bf16.bf16.f32 "
        "{%0,%1,%2,%3},{%4,%5,%6,%7},{%8,%9},{%0,%1,%2,%3};"
        : "+f"(c[0]), "+f"(c[1]), "+f"(c[2]), "+f"(c[3])
        : "r"(a[0]), "r"(a[1]), "r"(a[2]), "r"(a[3]), "r"(b[0]), "r"(b[1]));
}

// ---------------------------------------------------------------------------
// PREP (unchanged)
// ---------------------------------------------------------------------------
__global__ __launch_bounds__(256) void prep_kernel(
    const float* __restrict__ W1, const float* __restrict__ Wd)
{
    const int id = blockIdx.x * 256 + threadIdx.x;
    if (id < 81920) {
        const int r = id >> 9, c4 = id & 511;
        float4 v = *(const float4*)(W1 + (size_t)r * DIN + c4 * 4);
        uint2 h, l; splitf4(v, h, l);
        *(uint2*)(g_w1h + (size_t)r * DIN + c4 * 4) = h;
        *(uint2*)(g_w1l + (size_t)r * DIN + c4 * 4) = l;
    } else {
        const int id2 = id - 81920;
        const int r = id2 >> 5, c4 = id2 & 31;
        float4 v = *(const float4*)(Wd + (size_t)r * RNK + c4 * 4);
        uint2 h, l; splitf4(v, h, l);
        *(uint2*)(g_wdh + (size_t)r * RNK + c4 * 4) = h;
        *(uint2*)(g_wdl + (size_t)r * RNK + c4 * 4) = l;
    }
}

// ---------------------------------------------------------------------------
// GEMM1: W tiles via cp.async (pre-split, no conversion needed); X via
// register load + in-thread split. ONE barrier per K-iteration.
// ---------------------------------------------------------------------------
#define G1_AH 0
#define G1_AL 5120
#define G1_BH 10240
#define G1_BL 23040
#define G1_BUF 35840
#define G1_SMEM (2*G1_BUF)

__global__ __launch_bounds__(256, 2) void gemm1_kernel(const float* __restrict__ X)
{
    extern __shared__ __align__(16) char smem[];
    const unsigned sb = smem_u32(smem);
    const int tid = threadIdx.x, lane = tid & 31, w = tid >> 5;
    const int m0 = blockIdx.x * 64;
    const int wm = (w & 1) * 32;
    const int wn = (w >> 1) * 40;

    float acc[2][5][4];
#pragma unroll
    for (int i = 0; i < 2; i++)
#pragma unroll
        for (int j = 0; j < 5; j++)
#pragma unroll
            for (int q = 0; q < 4; q++) acc[i][j][q] = 0.f;

    const int rX0 = tid >> 3, cX0 = (tid & 7) * 4;
    const int rX1 = (tid + 256) >> 3;

    float4 xr[2];

    auto load_X = [&](int k0) {
        xr[0] = *(const float4*)(X + (size_t)(m0 + rX0) * DIN + k0 + cX0);
        xr[1] = *(const float4*)(X + (size_t)(m0 + rX1) * DIN + k0 + cX0);
    };
    auto store_X = [&](int bi) {
        char* buf = smem + bi * G1_BUF;
        uint2 h, l; splitf4(xr[0], h, l);
        *(uint2*)(buf + G1_AH + 80 * rX0 + 2 * cX0) = h;
        *(uint2*)(buf + G1_AL + 80 * rX0 + 2 * cX0) = l;
        splitf4(xr[1], h, l);
        *(uint2*)(buf + G1_AH + 80 * rX1 + 2 * cX0) = h;
        *(uint2*)(buf + G1_AL + 80 * rX1 + 2 * cX0) = l;
    };
    auto loadW = [&](int k0, int bi) {
        char* buf = smem + bi * G1_BUF;
#pragma unroll
        for (int q = 0; q < 5; q++) {
            const int id = q * 256 + tid;
            const __nv_bfloat16* src = (id < 640) ? g_w1h : g_w1l;
            const int off = (id < 640) ? G1_BH : G1_BL;
            const int rid = (id < 640) ? id : id - 640;
            const int r = rid >> 2, c16 = rid & 3;
            CP_ASYNC16(smem_u32(buf + off + 80 * r + 16 * c16),
                       src + (size_t)r * DIN + k0 + c16 * 8);
        }
        CP_COMMIT();
    };
    auto compute = [&](int bi) {
        const unsigned base = sb + bi * G1_BUF;
#pragma unroll
        for (int ks = 0; ks < 2; ks++) {
            const int kc = ks * 16 + ((lane >> 4) & 1) * 8;
            unsigned ah[2][4], al[2][4];
#pragma unroll
            for (int mt = 0; mt < 2; mt++) {
                const int row = wm + mt * 16 + (lane & 15);
                const unsigned ad = base + 80u * row + 2u * kc;
                ldsm_x4(ah[mt], ad + G1_AH);
                ldsm_x4(al[mt], ad + G1_AL);
            }
            unsigned bh[5][2], bl[5][2];
#pragma unroll
            for (int nt = 0; nt < 5; nt++) {
                const int row = wn + nt * 8 + (lane & 7);
                const int col = ks * 16 + ((lane >> 3) & 1) * 8;
                const unsigned bd = base + 80u * row + 2u * col;
                ldsm_x2(bh[nt], bd + G1_BH);
                ldsm_x2(bl[nt], bd + G1_BL);
            }
#pragma unroll
            for (int mt = 0; mt < 2; mt++)
#pragma unroll
                for (int nt = 0; nt < 5; nt++) {
                    mma_bf16(acc[mt][nt], ah[mt], bh[nt]);
                    mma_bf16(acc[mt][nt], ah[mt], bl[nt]);
                    mma_bf16(acc[mt][nt], al[mt], bh[nt]);
                }
        }
    };

    // prologue: fill buffer 0
    load_X(0);
    loadW(0, 0);
    store_X(0);
    CP_WAIT0();
    __syncthreads();

    for (int it = 0; it < 64; it++) {
        const int buf = it & 1;
        if (it + 1 < 64) {
            load_X((it + 1) * 32);          // LDG in flight during compute
            loadW((it + 1) * 32, buf ^ 1);  // async into other buffer (readers done at it-1)
        }
        compute(buf);
        if (it + 1 < 64) {
            store_X(buf ^ 1);               // safe: buf^1 readers passed previous barrier
            CP_WAIT0();
            __syncthreads();                // single barrier per iteration
        }
    }

#pragma unroll
    for (int mt = 0; mt < 2; mt++) {
#pragma unroll
        for (int nt = 0; nt < 5; nt++) {
            const int cb = wn + nt * 8 + 2 * (lane & 3);
            const int mA = m0 + wm + mt * 16 + (lane >> 2);
            const float* c = acc[mt][nt];
            if (cb < RNK) {
                unsigned h, l;
                split2(c[0], c[1], h, l);
                *(unsigned*)(g_dth + (size_t)mA * RNK + cb) = h;
                *(unsigned*)(g_dtl + (size_t)mA * RNK + cb) = l;
                split2(c[2], c[3], h, l);
                *(unsigned*)(g_dth + (size_t)(mA + 8) * RNK + cb) = h;
                *(unsigned*)(g_dtl + (size_t)(mA + 8) * RNK + cb) = l;
            } else if (cb < RNK + NST) {
                *(float2*)(g_B + (size_t)mA * NST + (cb - RNK)) = make_float2(c[0], c[1]);
                *(float2*)(g_B + (size_t)(mA + 8) * NST + (cb - RNK)) = make_float2(c[2], c[3]);
            } else {
                *(float2*)(g_C + (size_t)mA * NST + (cb - RNK - NST)) = make_float2(c[0], c[1]);
                *(float2*)(g_C + (size_t)(mA + 8) * NST + (cb - RNK - NST)) = make_float2(c[2], c[3]);
            }
        }
    }
}

// ---------------------------------------------------------------------------
// GEMM2: tile loads via cp.async (all operands pre-split in gmem).
// ---------------------------------------------------------------------------
#define G2_AH 0
#define G2_AL 17408
#define G2_BH 34816
#define G2_BL 69632
#define G2_SMEM 104448

__global__ __launch_bounds__(256, 2) void gemm2_kernel(const float* __restrict__ bias)
{
    extern __shared__ __align__(16) char smem[];
    const unsigned sb = smem_u32(smem);
    const int tid = threadIdx.x, lane = tid & 31, w = tid >> 5;
    const int mt_ = blockIdx.x >> 4;
    const int nt_ = blockIdx.x & 15;
    const int m0 = mt_ * 64, d0 = nt_ * 128;
    const int wm = (w & 1) * 32;
    const int wn = (w >> 1) * 32;

#pragma unroll
    for (int q = 0; q < 8; q++) {
        const int id = q * 256 + tid;
        const __nv_bfloat16* src = (id < 1024) ? g_dth : g_dtl;
        const int off = (id < 1024) ? G2_AH : G2_AL;
        const int rid = id & 1023;
        const int r = rid >> 4, c16 = rid & 15;
        CP_ASYNC16(smem_u32(smem + off + 272 * r + 16 * c16),
                   src + (size_t)(m0 + r) * RNK + c16 * 8);
    }
#pragma unroll
    for (int q = 0; q < 16; q++) {
        const int id = q * 256 + tid;
        const __nv_bfloat16* src = (id < 2048) ? g_wdh : g_wdl;
        const int off = (id < 2048) ? G2_BH : G2_BL;
        const int rid = id & 2047;
        const int r = rid >> 4, c16 = rid & 15;
        CP_ASYNC16(smem_u32(smem + off + 272 * r + 16 * c16),
                   src + (size_t)(d0 + r) * RNK + c16 * 8);
    }
    CP_COMMIT();
    CP_WAIT0();
    __syncthreads();

    float acc[2][4][4];
#pragma unroll
    for (int i = 0; i < 2; i++)
#pragma unroll
        for (int j = 0; j < 4; j++)
#pragma unroll
            for (int q = 0; q < 4; q++) acc[i][j][q] = 0.f;

#pragma unroll
    for (int ks = 0; ks < 8; ks++) {
        const int kc = ks * 16 + ((lane >> 4) & 1) * 8;
        unsigned ah[2][4], al[2][4];
#pragma unroll
        for (int mt = 0; mt < 2; mt++) {
            const int row = wm + mt * 16 + (lane & 15);
            const unsigned ad = sb + 272u * row + 2u * kc;
            ldsm_x4(ah[mt], ad + G2_AH);
            ldsm_x4(al[mt], ad + G2_AL);
        }
        unsigned bh[4][2], bl[4][2];
#pragma unroll
        for (int nt = 0; nt < 4; nt++) {
            const int row = wn + nt * 8 + (lane & 7);
            const int col = ks * 16 + ((lane >> 3) & 1) * 8;
            const unsigned bd = sb + 272u * row + 2u * col;
            ldsm_x2(bh[nt], bd + G2_BH);
            ldsm_x2(bl[nt], bd + G2_BL);
        }
#pragma unroll
        for (int mt = 0; mt < 2; mt++)
#pragma unroll
            for (int nt = 0; nt < 4; nt++) {
                mma_bf16(acc[mt][nt], ah[mt], bh[nt]);
                mma_bf16(acc[mt][nt], ah[mt], bl[nt]);
                mma_bf16(acc[mt][nt], al[mt], bh[nt]);
            }
    }

#pragma unroll
    for (int mt = 0; mt < 2; mt++) {
#pragma unroll
        for (int nt = 0; nt < 4; nt++) {
            const int d = d0 + wn + nt * 8 + 2 * (lane & 3);
            const int mA = m0 + wm + mt * 16 + (lane >> 2);
            const float b0v = bias[d], b1v = bias[d + 1];
            const float* c = acc[mt][nt];
            float z0 = c[0] + b0v, z1 = c[1] + b1v;
            float z2 = c[2] + b0v, z3 = c[3] + b1v;
            z0 = (z0 > 20.f) ? z0 : log1pf(__expf(z0));
            z1 = (z1 > 20.f) ? z1 : log1pf(__expf(z1));
            z2 = (z2 > 20.f) ? z2 : log1pf(__expf(z2));
            z3 = (z3 > 20.f) ? z3 : log1pf(__expf(z3));
            *(float2*)(g_delta + (size_t)mA * DIN + d) = make_float2(z0, z1);
            *(float2*)(g_delta + (size_t)(mA + 8) * DIN + d) = make_float2(z2, z3);
        }
    }
}

// ---------------------------------------------------------------------------
// Scan (P_SEG=16, round-11 version): 1 thread/channel, packed f32x2 states,
// cp.async double-buffered staging, direct coalesced y stores.
// ---------------------------------------------------------------------------
__device__ __forceinline__ void load_A16(const float* A_log, int d, float* A) {
#pragma unroll
    for (int q = 0; q < 4; q++) {
        float4 v = *(const float4*)(A_log + (size_t)d * NST + 4 * q);
        A[4*q+0] = -__expf(v.x); A[4*q+1] = -__expf(v.y);
        A[4*q+2] = -__expf(v.z); A[4*q+3] = -__expf(v.w);
    }
}

__global__ __launch_bounds__(CPB, 5) void scan_seg1_kernel(
    const float* __restrict__ x, const float* __restrict__ A_log)
{
    __shared__ __align__(16) float xs [2][SCH][CPB];
    __shared__ __align__(16) float dsm[2][SCH][CPB];
    __shared__ __align__(16) float Bs [2][SCH][16];

    const int tid  = threadIdx.x;
    const int dg   = blockIdx.x & 15;
    const int bseg = blockIdx.x >> 4;
    const int b    = bseg >> 4;
    const int seg  = bseg & 15;
    const int d    = dg * CPB + tid;

    unsigned fast;
    {
        float A[16];
        load_A16(A_log, d, A);
        bool ok = fabsf(A[0] + 1.f) < 2e-3f;
#pragma unroll
        for (int i = 1; i < 16; i++) ok = ok && (fabsf(A[i] - A[i-1] + 1.f) < 2e-3f);
        fast = __all_sync(0xffffffffu, ok);
    }

    const size_t t0 = (size_t)b * LEN + (size_t)seg * SEGLEN;
    const float* xg  = x       + t0 * DIN + dg * CPB;
    const float* dgp = g_delta + t0 * DIN + dg * CPB;
    const float* Bg  = g_B     + t0 * NST;

    const int rA = tid >> 5;              // rows rA, rA+4, rA+8, rA+12
    const int qA = (tid & 31) * 4;
    const int rB = (tid & 63) >> 2;
    const int qB = (tid & 3) * 4;

    auto issue = [&](int c, int buf) {
        const size_t off = (size_t)c * SCH;
#pragma unroll
        for (int q = 0; q < 4; q++) {
            const int row = rA + 4 * q;
            CP_ASYNC16(smem_u32(&xs [buf][row][qA]), xg  + (off + row) * DIN + qA);
            CP_ASYNC16(smem_u32(&dsm[buf][row][qA]), dgp + (off + row) * DIN + qA);
        }
        if (tid < 64)
            CP_ASYNC16(smem_u32(&Bs[buf][rB][qB]), Bg + (off + rB) * NST + qB);
        CP_COMMIT();
    };

    u64 h2[8];
#pragma unroll
    for (int i = 0; i < 8; i++) h2[i] = 0ull;
    float Sd = 0.f;

    issue(0, 0);
    for (int c = 0; c < NCHS; c++) {
        const int buf = c & 1;
        CP_WAIT0();
        __syncthreads();
        if (c + 1 < NCHS) issue(c + 1, buf ^ 1);

        if (fast) {
#pragma unroll
            for (int j = 0; j < SCH; j++) {
                const float dv = dsm[buf][j][tid];
                const float xv = xs [buf][j][tid];
                F4U2 bb[4];
#pragma unroll
                for (int q = 0; q < 4; q++) bb[q].f4 = *(const float4*)&Bs[buf][j][4 * q];
                const float r = __expf(-dv);
                const float s = dv * xv;
                Sd += dv;
                const u64 s2 = pack2f(s, s);
                u64 e2[8]; pow16p(r, e2);
#pragma unroll
                for (int i = 0; i < 8; i++)
                    h2[i] = ffma2(e2[i], h2[i], mul2(s2, bb[i >> 1].u2[i & 1]));
            }
        } else {
            float A[16];
            load_A16(A_log, d, A);
#pragma unroll
            for (int j = 0; j < SCH; j++) {
                const float dv = dsm[buf][j][tid];
                const float xv = xs [buf][j][tid];
                float Bv[16];
#pragma unroll
                for (int q = 0; q < 4; q++)
                    *(float4*)&Bv[4 * q] = *(const float4*)&Bs[buf][j][4 * q];
                const float s = dv * xv;
                Sd += dv;
#pragma unroll
                for (int i = 0; i < 8; i++) {
                    float2 hh = unpack2f(h2[i]);
                    hh.x = fmaf(__expf(dv * A[2*i]),   hh.x, s * Bv[2*i]);
                    hh.y = fmaf(__expf(dv * A[2*i+1]), hh.y, s * Bv[2*i+1]);
                    h2[i] = pack2f(hh.x, hh.y);
                }
            }
        }
    }

    u64 p2[8];
    if (fast) {
        pow16p(__expf(-Sd), p2);
    } else {
        float A[16];
        load_A16(A_log, d, A);
#pragma unroll
        for (int i = 0; i < 8; i++)
            p2[i] = pack2f(__expf(A[2*i] * Sd), __expf(A[2*i+1] * Sd));
    }
    const size_t hb = (((size_t)(b * P_SEG + seg) * DIN) + d) * NST;
#pragma unroll
    for (int q = 0; q < 4; q++) {
        float2 a = unpack2f(h2[2*q]),   bq = unpack2f(h2[2*q+1]);
        *(float4*)(g_hseg + hb + 4 * q) = make_float4(a.x, a.y, bq.x, bq.y);
        a = unpack2f(p2[2*q]); bq = unpack2f(p2[2*q+1]);
        *(float4*)(g_pseg + hb + 4 * q) = make_float4(a.x, a.y, bq.x, bq.y);
    }
}

__global__ __launch_bounds__(256) void scan_comb_kernel()
{
    const int tid  = threadIdx.x;
    const int cidx = blockIdx.x * 64 + (tid >> 2);
    const int ng   = tid & 3;
    const int b    = cidx >> 11;
    const int d    = cidx & (DIN - 1);

    float4 h = make_float4(0.f, 0.f, 0.f, 0.f);
#pragma unroll
    for (int s = 0; s < P_SEG; s++) {
        const size_t idx = (((size_t)(b * P_SEG + s) * DIN) + d) * NST + 4 * ng;
        *(float4*)(g_hin + idx) = h;
        const float4 Pv = *(const float4*)(g_pseg + idx);
        const float4 Lv = *(const float4*)(g_hseg + idx);
        h.x = fmaf(Pv.x, h.x, Lv.x);
        h.y = fmaf(Pv.y, h.y, Lv.y);
        h.z = fmaf(Pv.z, h.z, Lv.z);
        h.w = fmaf(Pv.w, h.w, Lv.w);
    }
}

__global__ __launch_bounds__(CPB, 5) void scan_seg2_kernel(
    const float* __restrict__ x, const float* __restrict__ A_log,
    const float* __restrict__ Dpar, float* __restrict__ out)
{
    __shared__ __align__(16) float xs [2][SCH][CPB];
    __shared__ __align__(16) float dsm[2][SCH][CPB];
    __shared__ __align__(16) float Bs [2][SCH][16];
    __shared__ __align__(16) float Cs [2][SCH][16];

    const int tid  = threadIdx.x;
    const int dg   = blockIdx.x & 15;
    const int bseg = blockIdx.x >> 4;
    const int b    = bseg >> 4;
    const int seg  = bseg & 15;
    const int d    = dg * CPB + tid;

    unsigned fast;
    {
        float A[16];
        load_A16(A_log, d, A);
        bool ok = fabsf(A[0] + 1.f) < 2e-3f;
#pragma unroll
        for (int i = 1; i < 16; i++) ok = ok && (fabsf(A[i] - A[i-1] + 1.f) < 2e-3f);
        fast = __all_sync(0xffffffffu, ok);
    }
    const float Dd = Dpar[d];

    const size_t t0 = (size_t)b * LEN + (size_t)seg * SEGLEN;
    const float* xg  = x       + t0 * DIN + dg * CPB;
    const float* dgp = g_delta + t0 * DIN + dg * CPB;
    const float* Bg  = g_B     + t0 * NST;
    const float* Cg  = g_C     + t0 * NST;
    float*       og  = out     + t0 * DIN + dg * CPB + tid;

    const int rA = tid >> 5;
    const int qA = (tid & 31) * 4;
    const int rB = (tid & 63) >> 2;
    const int qB = (tid & 3) * 4;

    auto issue = [&](int c, int buf) {
        const size_t off = (size_t)c * SCH;
#pragma unroll
        for (int q = 0; q < 4; q++) {
            const int row = rA + 4 * q;
            CP_ASYNC16(smem_u32(&xs [buf][row][qA]), xg  + (off + row) * DIN + qA);
            CP_ASYNC16(smem_u32(&dsm[buf][row][qA]), dgp + (off + row) * DIN + qA);
        }
        if (tid < 64)
            CP_ASYNC16(smem_u32(&Bs[buf][rB][qB]), Bg + (off + rB) * NST + qB);
        else if (tid < 128)
            CP_ASYNC16(smem_u32(&Cs[buf][rB][qB]), Cg + (off + rB) * NST + qB);
        CP_COMMIT();
    };

    u64 h2[8];
    const size_t hb = (((size_t)(b * P_SEG + seg) * DIN) + d) * NST;
#pragma unroll
    for (int q = 0; q < 4; q++) {
        F4U2 t; t.f4 = *(const float4*)(g_hin + hb + 4 * q);
        h2[2*q]   = t.u2[0];
        h2[2*q+1] = t.u2[1];
    }

    issue(0, 0);
    for (int c = 0; c < NCHS; c++) {
        const int buf = c & 1;
        CP_WAIT0();
        __syncthreads();
        if (c + 1 < NCHS) issue(c + 1, buf ^ 1);
        const size_t off = (size_t)c * SCH;

        if (fast) {
#pragma unroll
            for (int j = 0; j < SCH; j++) {
                const float dv = dsm[buf][j][tid];
                const float xv = xs [buf][j][tid];
                F4U2 bb[4], cc[4];
#pragma unroll
                for (int q = 0; q < 4; q++) {
                    bb[q].f4 = *(const float4*)&Bs[buf][j][4 * q];
                    cc[q].f4 = *(const float4*)&Cs[buf][j][4 * q];
                }
                const float r = __expf(-dv);
                const float s = dv * xv;
                const u64 s2 = pack2f(s, s);
                u64 e2[8]; pow16p(r, e2);
                u64 y2 = 0ull;
#pragma unroll
                for (int i = 0; i < 8; i++) {
                    h2[i] = ffma2(e2[i], h2[i], mul2(s2, bb[i >> 1].u2[i & 1]));
                    y2 = ffma2(h2[i], cc[i >> 1].u2[i & 1], y2);
                }
                const float2 yy = unpack2f(y2);
                og[(off + j) * DIN] = fmaf(Dd, xv, yy.x + yy.y);
            }
        } else {
            float A[16];
            load_A16(A_log, d, A);
#pragma unroll
            for (int j = 0; j < SCH; j++) {
                const float dv = dsm[buf][j][tid];
                const float xv = xs [buf][j][tid];
                float Bv[16], Cv[16];
#pragma unroll
                for (int q = 0; q < 4; q++) {
                    *(float4*)&Bv[4 * q] = *(const float4*)&Bs[buf][j][4 * q];
                    *(float4*)&Cv[4 * q] = *(const float4*)&Cs[buf][j][4 * q];
                }
                const float s = dv * xv;
                float y = 0.f;
#pragma unroll
                for (int i = 0; i < 8; i++) {
                    float2 hh = unpack2f(h2[i]);
                    hh.x = fmaf(__expf(dv * A[2*i]),   hh.x, s * Bv[2*i]);
                    hh.y = fmaf(__expf(dv * A[2*i+1]), hh.y, s * Bv[2*i+1]);
                    y = fmaf(hh.x, Cv[2*i], y);
                    y = fmaf(hh.y, Cv[2*i+1], y);
                    h2[i] = pack2f(hh.x, hh.y);
                }
                og[(off + j) * DIN] = fmaf(Dd, xv, y);
            }
        }
    }
}

// ---------------------------------------------------------------------------
// Launch
// ---------------------------------------------------------------------------
extern "C" void kernel_launch(void* const* d_in, const int* in_sizes, int n_in,
                              void* d_out, int out_size)
{
    const float* x         = (const float*)d_in[0];
    const float* A_log     = (const float*)d_in[1];
    const float* D_param   = (const float*)d_in[2];
    const float* x_proj_w  = (const float*)d_in[3];
    const float* dt_proj_w = (const float*)d_in[4];
    const float* dt_proj_b = (const float*)d_in[5];
    float* out = (float*)d_out;

    cudaFuncSetAttribute(gemm1_kernel, cudaFuncAttributeMaxDynamicSharedMemorySize, G1_SMEM);
    cudaFuncSetAttribute(gemm2_kernel, cudaFuncAttributeMaxDynamicSharedMemorySize, G2_SMEM);

    prep_kernel<<<576, 256>>>(x_proj_w, dt_proj_w);
    gemm1_kernel<<<M_TOT / 64, 256, G1_SMEM>>>(x);
    gemm2_kernel<<<(M_TOT / 64) * (DIN / 128), 256, G2_SMEM>>>(dt_proj_b);
    scan_seg1_kernel<<<BATCH * P_SEG * (DIN / CPB), CPB>>>(x, A_log);
    scan_comb_kernel<<<BATCH * DIN / 64, 256>>>();
    scan_seg2_kernel<<<BATCH * P_SEG * (DIN / CPB), CPB>>>(x, A_log, D_param, out);
}